// round 16
// baseline (speedup 1.0000x reference)
#include <cuda_runtime.h>
#include <cuda_fp16.h>
#include <cstdint>

// Problem constants
#define TOK     2048
#define DMODEL  1024
#define DINNER  2048
#define DSTATE  16
#define SEQLEN  1024
#define NBATCH  2
#define NIN     (3 * DINNER)
#define CHK     16
#define CHL     (SEQLEN / CHK)
#define NSLOT   (NBATCH * DINNER)
#define NSS     (NSLOT * DSTATE)

#define LOG2E 1.4426950408889634f

// ---------------------------------------------------------------------------
// Device-global scratch (fp16 intermediates)
// ---------------------------------------------------------------------------
__device__ __half g_xproj[TOK * DINNER];
__device__ __half g_delta[TOK * DINNER];
__device__ __half g_gate [TOK * DINNER];

__device__ float g_P[CHK * NSS];
__device__ float g_q[CHK * NSS];

__device__ __half g_x  [TOK * DMODEL];
__device__ __half g_wi [NIN * DMODEL];
__device__ __half g_wo [DMODEL * DINNER];
__device__ __half g_gss[TOK * DINNER];

// ---------------------------------------------------------------------------
// Side stream + events for forked-capture overlap (created at program start,
// before any harness memory checkpoint; reused identically on every call).
// ---------------------------------------------------------------------------
struct AuxStreams {
    cudaStream_t side;
    cudaEvent_t  evFork, evJoin;
    AuxStreams() {
        cudaStreamCreateWithFlags(&side, cudaStreamNonBlocking);
        cudaEventCreateWithFlags(&evFork, cudaEventDisableTiming);
        cudaEventCreateWithFlags(&evJoin, cudaEventDisableTiming);
    }
};
static AuxStreams g_aux;

// ---------------------------------------------------------------------------
// PTX helpers
// ---------------------------------------------------------------------------
__device__ __forceinline__ uint32_t smem_u32(const void* p) {
    uint32_t a;
    asm("{ .reg .u64 t; cvta.to.shared.u64 t, %1; cvt.u32.u64 %0, t; }" : "=r"(a) : "l"(p));
    return a;
}
__device__ __forceinline__ void cpa16(uint32_t s, const void* g) {
    asm volatile("cp.async.cg.shared.global [%0], [%1], 16;" :: "r"(s), "l"(g) : "memory");
}
__device__ __forceinline__ void cpa_commit() {
    asm volatile("cp.async.commit_group;" ::: "memory");
}
template <int N>
__device__ __forceinline__ void cpa_wait() {
    asm volatile("cp.async.wait_group %0;" :: "n"(N) : "memory");
}
__device__ __forceinline__ void ldsm4(uint32_t& r0, uint32_t& r1, uint32_t& r2,
                                      uint32_t& r3, uint32_t a) {
    asm volatile("ldmatrix.sync.aligned.m8n8.x4.shared.b16 {%0,%1,%2,%3}, [%4];"
                 : "=r"(r0), "=r"(r1), "=r"(r2), "=r"(r3) : "r"(a));
}
__device__ __forceinline__ void mma16816(float* d, const uint32_t* a, const uint32_t* b) {
    asm volatile(
        "mma.sync.aligned.m16n8k16.row.col.f32.f16.f16.f32 "
        "{%0,%1,%2,%3}, {%4,%5,%6,%7}, {%8,%9}, {%0,%1,%2,%3};"
        : "+f"(d[0]), "+f"(d[1]), "+f"(d[2]), "+f"(d[3])
        : "r"(a[0]), "r"(a[1]), "r"(a[2]), "r"(a[3]), "r"(b[0]), "r"(b[1]));
}

// Fast exp on FMA/ALU pipes (GEMM epilogue sigmoid only)
__device__ __forceinline__ float fexp(float z) {
    float nf = rintf(z * LOG2E);
    float r  = fmaf(nf, -0.693145751953125f, z);
    r        = fmaf(nf, -1.42860677e-6f, r);
    float p  = 1.0f / 720.0f;
    p = fmaf(p, r, 1.0f / 120.0f);
    p = fmaf(p, r, 1.0f / 24.0f);
    p = fmaf(p, r, 1.0f / 6.0f);
    p = fmaf(p, r, 0.5f);
    p = fmaf(p, r, 1.0f);
    p = fmaf(p, r, 1.0f);
    float s = __int_as_float(((int)nf + 127) << 23);
    return p * s;
}

// ---------------------------------------------------------------------------
// GEMM SMEM: stage = A (BM rows) ++ W (128 rows), 80B rows, TRIPLE buffered
// ---------------------------------------------------------------------------
#define ROWB 80
#define SMEMT(BM) (3 * ((BM) * ROWB + 128 * ROWB) + 512)

template <int ROWS>
__device__ __forceinline__ void tile_cpasync(const __half* __restrict__ g,
                                             int rowBase, int kt, int ld,
                                             uint32_t sdst, int tid) {
#pragma unroll
    for (int i = 0; i < ROWS / 64; i++) {
        int seg = tid + i * 256;
        int r   = seg >> 2;
        int c   = seg & 3;
        cpa16(sdst + r * ROWB + c * 16,
              g + (size_t)(rowBase + r) * ld + kt + c * 8);
    }
}

// ---------------------------------------------------------------------------
// fp16 GEMM: C = A @ W^T + bias ; 3-stage cp.async pipeline, 1 sync/iter
// EPI 0 (N=4096): fp16 stores -> xproj (col<2048) | relu->delta
// EPI 1 (N=2048): sigmoid -> gate (fp16)
// EPI 2: +bias -> Cout (fp32)
// ---------------------------------------------------------------------------
template <int EPI, int BM>
__global__ void __launch_bounds__(256, 2)
gemm_mma(const __half* __restrict__ A, const __half* __restrict__ W,
         const float* __restrict__ bias, float* __restrict__ Cout, int N, int K)
{
    constexpr int MI     = BM / 32;
    constexpr int ATILE  = BM * ROWB;
    constexpr int BTILE  = 128 * ROWB;
    constexpr int STAGE  = ATILE + BTILE;
    constexpr int BIASOF = 3 * STAGE;

    extern __shared__ char smem[];
    uint32_t sbase = smem_u32(smem);

    const int tid = threadIdx.x;
    const int wid = tid >> 5;
    const int l   = tid & 31;
    const int wm  = wid >> 2;
    const int wn  = wid & 3;
    const int mo  = wm * (BM / 2);
    const int no  = wn * 32;

    const int rowBase = blockIdx.y * BM;
    const int colBase = blockIdx.x * 128;

    if (tid < 128)
        *reinterpret_cast<float*>(smem + BIASOF + tid * 4) = bias[colBase + tid];

    const uint32_t aRow = (uint32_t)((mo + (l & 15)) * ROWB + ((l >> 4) * 16));
    const uint32_t bRow = (uint32_t)((no + (l & 7) + ((l & 16) ? 8 : 0)) * ROWB
                                     + (((l >> 3) & 1) * 16));

    float acc[MI][4][4];
#pragma unroll
    for (int mi = 0; mi < MI; mi++)
#pragma unroll
        for (int ni = 0; ni < 4; ni++)
#pragma unroll
            for (int r = 0; r < 4; r++) acc[mi][ni][r] = 0.0f;

    const int NC = K / 32;

    {
        tile_cpasync<BM >(A, rowBase, 0, K, sbase,         tid);
        tile_cpasync<128>(W, colBase, 0, K, sbase + ATILE, tid);
        cpa_commit();
        tile_cpasync<BM >(A, rowBase, 32, K, sbase + STAGE,         tid);
        tile_cpasync<128>(W, colBase, 32, K, sbase + STAGE + ATILE, tid);
        cpa_commit();
    }

    for (int c = 0; c < NC; c++) {
        if (c + 1 < NC) cpa_wait<1>();
        else            cpa_wait<0>();
        __syncthreads();

        if (c + 2 < NC) {
            uint32_t st = sbase + ((c + 2) % 3) * STAGE;
            int kt = (c + 2) * 32;
            tile_cpasync<BM >(A, rowBase, kt, K, st,         tid);
            tile_cpasync<128>(W, colBase, kt, K, st + ATILE, tid);
            cpa_commit();
        }

        uint32_t st = sbase + (c % 3) * STAGE;
#pragma unroll
        for (int ks = 0; ks < 2; ks++) {
            uint32_t ah[MI][4], bh[8];
#pragma unroll
            for (int mi = 0; mi < MI; mi++) {
                uint32_t ad = st + aRow + mi * (16 * ROWB) + ks * 32;
                ldsm4(ah[mi][0], ah[mi][1], ah[mi][2], ah[mi][3], ad);
            }
#pragma unroll
            for (int np = 0; np < 2; np++) {
                uint32_t bd = st + ATILE + bRow + np * (16 * ROWB) + ks * 32;
                ldsm4(bh[np * 4 + 0], bh[np * 4 + 1], bh[np * 4 + 2], bh[np * 4 + 3], bd);
            }
#pragma unroll
            for (int mi = 0; mi < MI; mi++)
#pragma unroll
                for (int ni = 0; ni < 4; ni++)
                    mma16816(acc[mi][ni], ah[mi], &bh[ni * 2]);
        }
    }

    __syncthreads();
    const float* sb = reinterpret_cast<const float*>(smem + BIASOF);
    const int g  = l >> 2;
    const int t4 = l & 3;
#pragma unroll
    for (int mi = 0; mi < MI; mi++) {
#pragma unroll
        for (int ni = 0; ni < 4; ni++) {
            int bc   = no + ni * 8 + 2 * t4;
            int col  = colBase + bc;
            int row0 = rowBase + mo + mi * 16 + g;
            int row1 = row0 + 8;
            float2 v0, v1;
            v0.x = acc[mi][ni][0] + sb[bc];
            v0.y = acc[mi][ni][1] + sb[bc + 1];
            v1.x = acc[mi][ni][2] + sb[bc];
            v1.y = acc[mi][ni][3] + sb[bc + 1];
            if (EPI == 0) {
                if (colBase < DINNER) {
                    *reinterpret_cast<__half2*>(&g_xproj[(size_t)row0 * DINNER + col]) =
                        __floats2half2_rn(v0.x, v0.y);
                    *reinterpret_cast<__half2*>(&g_xproj[(size_t)row1 * DINNER + col]) =
                        __floats2half2_rn(v1.x, v1.y);
                } else {
                    int cc = col - DINNER;
                    *reinterpret_cast<__half2*>(&g_delta[(size_t)row0 * DINNER + cc]) =
                        __floats2half2_rn(fmaxf(v0.x, 0.f), fmaxf(v0.y, 0.f));
                    *reinterpret_cast<__half2*>(&g_delta[(size_t)row1 * DINNER + cc]) =
                        __floats2half2_rn(fmaxf(v1.x, 0.f), fmaxf(v1.y, 0.f));
                }
            } else if (EPI == 1) {
                *reinterpret_cast<__half2*>(&g_gate[(size_t)row0 * DINNER + col]) =
                    __floats2half2_rn(1.f / (1.f + fexp(-v0.x)),
                                      1.f / (1.f + fexp(-v0.y)));
                *reinterpret_cast<__half2*>(&g_gate[(size_t)row1 * DINNER + col]) =
                    __floats2half2_rn(1.f / (1.f + fexp(-v1.x)),
                                      1.f / (1.f + fexp(-v1.y)));
            } else {
                *reinterpret_cast<float2*>(&Cout[(size_t)row0 * N + col]) = v0;
                *reinterpret_cast<float2*>(&Cout[(size_t)row1 * N + col]) = v1;
            }
        }
    }
}

// ---------------------------------------------------------------------------
// Fused fp32 -> fp16 convert for all four source arrays (one launch)
// ---------------------------------------------------------------------------
#define CR0 (TOK * DMODEL / 8)
#define CR1 (2 * DINNER * DMODEL / 8)
#define CR2 (DINNER * DMODEL / 8)
#define CR3 (DMODEL * DINNER / 8)
#define CRT (CR0 + CR1 + CR2 + CR3)

__global__ void __launch_bounds__(256)
conv_all_kernel(const float4* __restrict__ sx, const float4* __restrict__ swi,
                const float4* __restrict__ swg, const float4* __restrict__ swo,
                uint4* __restrict__ dx, uint4* __restrict__ dwi,
                uint4* __restrict__ dwg, uint4* __restrict__ dwo)
{
    int i = blockIdx.x * blockDim.x + threadIdx.x;
    if (i >= CRT) return;
    const float4* s; uint4* d; int off;
    if (i < CR0)                   { s = sx;  d = dx;  off = i; }
    else if (i < CR0 + CR1)        { s = swi; d = dwi; off = i - CR0; }
    else if (i < CR0 + CR1 + CR2)  { s = swg; d = dwg; off = i - CR0 - CR1; }
    else                           { s = swo; d = dwo; off = i - CR0 - CR1 - CR2; }
    float4 u = s[2 * off];
    float4 v = s[2 * off + 1];
    __half2 h0 = __floats2half2_rn(u.x, u.y);
    __half2 h1 = __floats2half2_rn(u.z, u.w);
    __half2 h2 = __floats2half2_rn(v.x, v.y);
    __half2 h3 = __floats2half2_rn(v.z, v.w);
    uint4 o;
    o.x = *reinterpret_cast<uint32_t*>(&h0);
    o.y = *reinterpret_cast<uint32_t*>(&h1);
    o.z = *reinterpret_cast<uint32_t*>(&h2);
    o.w = *reinterpret_cast<uint32_t*>(&h3);
    d[off] = o;
}

// ---------------------------------------------------------------------------
// Chunked selective scan, 4 states/lane, 64 channels/CTA, fp16 SMEM staging.
// ---------------------------------------------------------------------------
#define SCW   64
#define SROWH 72

__global__ void __launch_bounds__(256)
scanA_kernel(const float* __restrict__ A_log, const float* __restrict__ B_mat)
{
    __shared__ __half sdel[CHL][SROWH];
    __shared__ __half sxp [CHL][SROWH];

    int tid   = threadIdx.x;
    int gidx0 = blockIdx.x * SCW;
    int chunk = gidx0 >> 12;
    int slot0 = gidx0 & (NSLOT - 1);
    int b     = slot0 >> 11;
    int ch0   = slot0 & (DINNER - 1);

    size_t base = (size_t)(b * SEQLEN + chunk * CHL) * DINNER + ch0;

#pragma unroll
    for (int it = 0; it < 2; it++) {
        int seg = tid + it * 256;
        int t   = seg >> 3;
        int c8  = (seg & 7) * 8;
        *reinterpret_cast<uint4*>(&sdel[t][c8]) =
            *reinterpret_cast<const uint4*>(&g_delta[base + (size_t)t * DINNER + c8]);
        *reinterpret_cast<uint4*>(&sxp[t][c8]) =
            *reinterpret_cast<const uint4*>(&g_xproj[base + (size_t)t * DINNER + c8]);
    }
    __syncthreads();

    int grp = tid >> 2;
    int s2  = tid & 3;
    int ch  = ch0 + grp;

    float As2[4], Bs[4];
#pragma unroll
    for (int j = 0; j < 4; j++) {
        int s = s2 * 4 + j;
        As2[j] = -__expf(A_log[ch * DSTATE + s]) * LOG2E;
        Bs[j]  = B_mat[ch * DSTATE + s];
    }

    float P[4] = {1.f, 1.f, 1.f, 1.f};
    float q[4] = {0.f, 0.f, 0.f, 0.f};
#pragma unroll 4
    for (int t = 0; t < CHL; t++) {
        float dt = __half2float(sdel[t][grp]);
        float xt = __half2float(sxp[t][grp]);
        float u  = dt * xt;
#pragma unroll
        for (int j = 0; j < 4; j++) {
            float a = exp2f(As2[j] * dt);
            q[j] = fmaf(q[j], a, u * Bs[j]);
            P[j] *= a;
        }
    }
    size_t o = (size_t)(gidx0 + grp) * DSTATE + s2 * 4;
    *reinterpret_cast<float4*>(&g_P[o]) = make_float4(P[0], P[1], P[2], P[3]);
    *reinterpret_cast<float4*>(&g_q[o]) = make_float4(q[0], q[1], q[2], q[3]);
}

__global__ void __launch_bounds__(256)
scanC_kernel(const float* __restrict__ A_log, const float* __restrict__ B_mat,
             const float* __restrict__ C_mat, const float* __restrict__ D_vec)
{
    __shared__ __half sdel[CHL][SROWH];
    __shared__ __half sxp [CHL][SROWH];
    __shared__ __half sgt [CHL][SROWH];
    __shared__ __half sout[CHL][SCW];

    int tid   = threadIdx.x;
    int gidx0 = blockIdx.x * SCW;
    int chunk = gidx0 >> 12;
    int slot0 = gidx0 & (NSLOT - 1);
    int b     = slot0 >> 11;
    int ch0   = slot0 & (DINNER - 1);

    size_t base = (size_t)(b * SEQLEN + chunk * CHL) * DINNER + ch0;

#pragma unroll
    for (int it = 0; it < 2; it++) {
        int seg = tid + it * 256;
        int t   = seg >> 3;
        int c8  = (seg & 7) * 8;
        *reinterpret_cast<uint4*>(&sdel[t][c8]) =
            *reinterpret_cast<const uint4*>(&g_delta[base + (size_t)t * DINNER + c8]);
        *reinterpret_cast<uint4*>(&sxp[t][c8]) =
            *reinterpret_cast<const uint4*>(&g_xproj[base + (size_t)t * DINNER + c8]);
        *reinterpret_cast<uint4*>(&sgt[t][c8]) =
            *reinterpret_cast<const uint4*>(&g_gate[base + (size_t)t * DINNER + c8]);
    }

    int grp  = tid >> 2;
    int s2   = tid & 3;
    int ch   = ch0 + grp;
    int slot = slot0 + grp;

    float As2[4], Bs[4], cs[4];
#pragma unroll
    for (int j = 0; j < 4; j++) {
        int s = s2 * 4 + j;
        As2[j] = -__expf(A_log[ch * DSTATE + s]) * LOG2E;
        Bs[j]  = B_mat[ch * DSTATE + s];
        cs[j]  = C_mat[s];
    }
    float Dch = D_vec[ch];

    float h[4] = {0.f, 0.f, 0.f, 0.f};
    for (int j = 0; j < chunk; j++) {
        size_t o = ((size_t)(j << 12) + slot) * DSTATE + s2 * 4;
        float4 P4 = *reinterpret_cast<const float4*>(&g_P[o]);
        float4 q4 = *reinterpret_cast<const float4*>(&g_q[o]);
        h[0] = fmaf(P4.x, h[0], q4.x);
        h[1] = fmaf(P4.y, h[1], q4.y);
        h[2] = fmaf(P4.z, h[2], q4.z);
        h[3] = fmaf(P4.w, h[3], q4.w);
    }

    __syncthreads();

#pragma unroll 4
    for (int t = 0; t < CHL; t++) {
        float dt = __half2float(sdel[t][grp]);
        float xt = __half2float(sxp[t][grp]);
        float u  = dt * xt;
        float p  = 0.f;
#pragma unroll
        for (int j = 0; j < 4; j++) {
            float a = exp2f(As2[j] * dt);
            h[j] = fmaf(h[j], a, u * Bs[j]);
            p = fmaf(h[j], cs[j], p);
        }
        p += __shfl_xor_sync(0xffffffffu, p, 1);
        p += __shfl_xor_sync(0xffffffffu, p, 2);
        if (s2 == 0) {
            float v = __half2float(sgt[t][grp]) * (p + xt * Dch);
            sout[t][grp] = __float2half(v);
        }
    }
    __syncthreads();

    {
        int t = tid >> 2;
        int c = (tid & 3) * 16;
        *reinterpret_cast<uint4*>(&g_gss[base + (size_t)t * DINNER + c]) =
            *reinterpret_cast<const uint4*>(&sout[t][c]);
        *reinterpret_cast<uint4*>(&g_gss[base + (size_t)t * DINNER + c + 8]) =
            *reinterpret_cast<const uint4*>(&sout[t][c + 8]);
    }
}

// ---------------------------------------------------------------------------
extern "C" void kernel_launch(void* const* d_in, const int* in_sizes, int n_in,
                              void* d_out, int out_size)
{
    const float* x      = (const float*)d_in[0];
    const float* W_in   = (const float*)d_in[1];
    const float* b_in   = (const float*)d_in[2];
    const float* W_gate = (const float*)d_in[3];
    const float* b_gate = (const float*)d_in[4];
    const float* W_out  = (const float*)d_in[5];
    const float* b_out  = (const float*)d_in[6];
    const float* A_log  = (const float*)d_in[7];
    const float* B_mat  = (const float*)d_in[8];
    const float* C_mat  = (const float*)d_in[9];
    const float* D_vec  = (const float*)d_in[10];
    float* out = (float*)d_out;

    cudaFuncSetAttribute((const void*)gemm_mma<0, 128>,
                         cudaFuncAttributeMaxDynamicSharedMemorySize, SMEMT(128));
    cudaFuncSetAttribute((const void*)gemm_mma<1, 128>,
                         cudaFuncAttributeMaxDynamicSharedMemorySize, SMEMT(128));
    cudaFuncSetAttribute((const void*)gemm_mma<2, 64>,
                         cudaFuncAttributeMaxDynamicSharedMemorySize, SMEMT(64));

    __half *xh, *wi, *wo, *gs;
    cudaGetSymbolAddress((void**)&xh, g_x);
    cudaGetSymbolAddress((void**)&wi, g_wi);
    cudaGetSymbolAddress((void**)&wo, g_wo);
    cudaGetSymbolAddress((void**)&gs, g_gss);

    const size_t WG_OFF = (size_t)2 * DINNER * DMODEL;

    // 1) fused fp32 -> fp16 converts
    conv_all_kernel<<<(CRT + 255) / 256, 256>>>(
        (const float4*)x, (const float4*)W_in, (const float4*)W_gate, (const float4*)W_out,
        (uint4*)xh, (uint4*)wi, (uint4*)(wi + WG_OFF), (uint4*)wo);

    // 2a) in-proj GEMM (xproj | delta, N = 4096)
    gemm_mma<0, 128><<<dim3(4096 / 128, TOK / 128), 256, SMEMT(128)>>>(
        xh, wi, b_in, nullptr, 2 * DINNER, DMODEL);

    // fork: gate GEMM on side stream, concurrent with scanA (disjoint pipes)
    cudaEventRecord(g_aux.evFork, 0);
    cudaStreamWaitEvent(g_aux.side, g_aux.evFork, 0);

    // 2b) gate GEMM (N = 2048) on side stream
    gemm_mma<1, 128><<<dim3(2048 / 128, TOK / 128), 256, SMEMT(128), g_aux.side>>>(
        xh, wi + WG_OFF, b_gate, nullptr, DINNER, DMODEL);

    // 3a) scanA on main stream (needs only xproj/delta)
    scanA_kernel<<<(CHK * NSLOT) / SCW, 256>>>(A_log, B_mat);

    // join: scanC needs gate
    cudaEventRecord(g_aux.evJoin, g_aux.side);
    cudaStreamWaitEvent(0, g_aux.evJoin, 0);

    // 3b) scanC (replay + gate + emit fp16)
    scanC_kernel<<<(CHK * NSLOT) / SCW, 256>>>(A_log, B_mat, C_mat, D_vec);

    // 4) out = gss @ W_out^T + b_out  (BM=64 -> 512 CTAs)
    gemm_mma<2, 64><<<dim3(DMODEL / 128, TOK / 64), 256, SMEMT(64)>>>(
        gs, wo, b_out, out, DMODEL, DINNER);
}

// round 17
// speedup vs baseline: 1.0416x; 1.0416x over previous
#include <cuda_runtime.h>
#include <cuda_fp16.h>
#include <cstdint>

// Problem constants
#define TOK     2048
#define DMODEL  1024
#define DINNER  2048
#define DSTATE  16
#define SEQLEN  1024
#define NBATCH  2
#define NIN     (3 * DINNER)
#define CHK     16
#define CHL     (SEQLEN / CHK)
#define NSLOT   (NBATCH * DINNER)
#define NSS     (NSLOT * DSTATE)

#define LOG2E 1.4426950408889634f

// ---------------------------------------------------------------------------
// Device-global scratch (fp16 intermediates)
// ---------------------------------------------------------------------------
__device__ __half g_xproj[TOK * DINNER];
__device__ __half g_delta[TOK * DINNER];
__device__ __half g_gate [TOK * DINNER];

__device__ float g_P[CHK * NSS];
__device__ float g_r[CHK * NSS];     // B-factored local state (q / Bs)

__device__ __half g_x  [TOK * DMODEL];
__device__ __half g_wi [NIN * DMODEL];
__device__ __half g_wo [DMODEL * DINNER];
__device__ __half g_gss[TOK * DINNER];

// ---------------------------------------------------------------------------
// PTX helpers
// ---------------------------------------------------------------------------
__device__ __forceinline__ uint32_t smem_u32(const void* p) {
    uint32_t a;
    asm("{ .reg .u64 t; cvta.to.shared.u64 t, %1; cvt.u32.u64 %0, t; }" : "=r"(a) : "l"(p));
    return a;
}
__device__ __forceinline__ void cpa16(uint32_t s, const void* g) {
    asm volatile("cp.async.cg.shared.global [%0], [%1], 16;" :: "r"(s), "l"(g) : "memory");
}
__device__ __forceinline__ void cpa_commit() {
    asm volatile("cp.async.commit_group;" ::: "memory");
}
template <int N>
__device__ __forceinline__ void cpa_wait() {
    asm volatile("cp.async.wait_group %0;" :: "n"(N) : "memory");
}
__device__ __forceinline__ void ldsm4(uint32_t& r0, uint32_t& r1, uint32_t& r2,
                                      uint32_t& r3, uint32_t a) {
    asm volatile("ldmatrix.sync.aligned.m8n8.x4.shared.b16 {%0,%1,%2,%3}, [%4];"
                 : "=r"(r0), "=r"(r1), "=r"(r2), "=r"(r3) : "r"(a));
}
__device__ __forceinline__ void mma16816(float* d, const uint32_t* a, const uint32_t* b) {
    asm volatile(
        "mma.sync.aligned.m16n8k16.row.col.f32.f16.f16.f32 "
        "{%0,%1,%2,%3}, {%4,%5,%6,%7}, {%8,%9}, {%0,%1,%2,%3};"
        : "+f"(d[0]), "+f"(d[1]), "+f"(d[2]), "+f"(d[3])
        : "r"(a[0]), "r"(a[1]), "r"(a[2]), "r"(a[3]), "r"(b[0]), "r"(b[1]));
}

// Fast exp on FMA/ALU pipes (GEMM epilogue sigmoid only)
__device__ __forceinline__ float fexp(float z) {
    float nf = rintf(z * LOG2E);
    float r  = fmaf(nf, -0.693145751953125f, z);
    r        = fmaf(nf, -1.42860677e-6f, r);
    float p  = 1.0f / 720.0f;
    p = fmaf(p, r, 1.0f / 120.0f);
    p = fmaf(p, r, 1.0f / 24.0f);
    p = fmaf(p, r, 1.0f / 6.0f);
    p = fmaf(p, r, 0.5f);
    p = fmaf(p, r, 1.0f);
    p = fmaf(p, r, 1.0f);
    float s = __int_as_float(((int)nf + 127) << 23);
    return p * s;
}

// ---------------------------------------------------------------------------
// GEMM SMEM: stage = A (BM rows) ++ W (128 rows), 80B rows, TRIPLE buffered
// ---------------------------------------------------------------------------
#define ROWB 80
#define SMEMT(BM) (3 * ((BM) * ROWB + 128 * ROWB) + 512)

template <int ROWS>
__device__ __forceinline__ void tile_cpasync(const __half* __restrict__ g,
                                             int rowBase, int kt, int ld,
                                             uint32_t sdst, int tid) {
#pragma unroll
    for (int i = 0; i < ROWS / 64; i++) {
        int seg = tid + i * 256;
        int r   = seg >> 2;
        int c   = seg & 3;
        cpa16(sdst + r * ROWB + c * 16,
              g + (size_t)(rowBase + r) * ld + kt + c * 8);
    }
}

// ---------------------------------------------------------------------------
// fp16 GEMM: C = A @ W^T + bias ; 3-stage cp.async pipeline, 1 sync/iter
// EPI 0 (N=6144): fp16 stores -> xproj | relu->delta | sigmoid->gate
// EPI 2: +bias -> Cout (fp32)
// ---------------------------------------------------------------------------
template <int EPI, int BM>
__global__ void __launch_bounds__(256, 2)
gemm_mma(const __half* __restrict__ A, const __half* __restrict__ W,
         const float* __restrict__ biasA, const float* __restrict__ biasB,
         float* __restrict__ Cout, int N, int K)
{
    constexpr int MI     = BM / 32;
    constexpr int ATILE  = BM * ROWB;
    constexpr int BTILE  = 128 * ROWB;
    constexpr int STAGE  = ATILE + BTILE;
    constexpr int BIASOF = 3 * STAGE;

    extern __shared__ char smem[];
    uint32_t sbase = smem_u32(smem);

    const int tid = threadIdx.x;
    const int wid = tid >> 5;
    const int l   = tid & 31;
    const int wm  = wid >> 2;
    const int wn  = wid & 3;
    const int mo  = wm * (BM / 2);
    const int no  = wn * 32;

    const int rowBase = blockIdx.y * BM;
    const int colBase = blockIdx.x * 128;

    if (tid < 128) {
        float bv;
        if (EPI == 0)
            bv = (colBase < 2 * DINNER) ? biasA[colBase + tid]
                                        : biasB[colBase - 2 * DINNER + tid];
        else
            bv = biasA[colBase + tid];
        *reinterpret_cast<float*>(smem + BIASOF + tid * 4) = bv;
    }

    const uint32_t aRow = (uint32_t)((mo + (l & 15)) * ROWB + ((l >> 4) * 16));
    const uint32_t bRow = (uint32_t)((no + (l & 7) + ((l & 16) ? 8 : 0)) * ROWB
                                     + (((l >> 3) & 1) * 16));

    float acc[MI][4][4];
#pragma unroll
    for (int mi = 0; mi < MI; mi++)
#pragma unroll
        for (int ni = 0; ni < 4; ni++)
#pragma unroll
            for (int r = 0; r < 4; r++) acc[mi][ni][r] = 0.0f;

    const int NC = K / 32;

    {
        tile_cpasync<BM >(A, rowBase, 0, K, sbase,         tid);
        tile_cpasync<128>(W, colBase, 0, K, sbase + ATILE, tid);
        cpa_commit();
        tile_cpasync<BM >(A, rowBase, 32, K, sbase + STAGE,         tid);
        tile_cpasync<128>(W, colBase, 32, K, sbase + STAGE + ATILE, tid);
        cpa_commit();
    }

    for (int c = 0; c < NC; c++) {
        if (c + 1 < NC) cpa_wait<1>();
        else            cpa_wait<0>();
        __syncthreads();

        if (c + 2 < NC) {
            uint32_t st = sbase + ((c + 2) % 3) * STAGE;
            int kt = (c + 2) * 32;
            tile_cpasync<BM >(A, rowBase, kt, K, st,         tid);
            tile_cpasync<128>(W, colBase, kt, K, st + ATILE, tid);
            cpa_commit();
        }

        uint32_t st = sbase + (c % 3) * STAGE;
#pragma unroll
        for (int ks = 0; ks < 2; ks++) {
            uint32_t ah[MI][4], bh[8];
#pragma unroll
            for (int mi = 0; mi < MI; mi++) {
                uint32_t ad = st + aRow + mi * (16 * ROWB) + ks * 32;
                ldsm4(ah[mi][0], ah[mi][1], ah[mi][2], ah[mi][3], ad);
            }
#pragma unroll
            for (int np = 0; np < 2; np++) {
                uint32_t bd = st + ATILE + bRow + np * (16 * ROWB) + ks * 32;
                ldsm4(bh[np * 4 + 0], bh[np * 4 + 1], bh[np * 4 + 2], bh[np * 4 + 3], bd);
            }
#pragma unroll
            for (int mi = 0; mi < MI; mi++)
#pragma unroll
                for (int ni = 0; ni < 4; ni++)
                    mma16816(acc[mi][ni], ah[mi], &bh[ni * 2]);
        }
    }

    __syncthreads();
    const float* sb = reinterpret_cast<const float*>(smem + BIASOF);
    const int g  = l >> 2;
    const int t4 = l & 3;
#pragma unroll
    for (int mi = 0; mi < MI; mi++) {
#pragma unroll
        for (int ni = 0; ni < 4; ni++) {
            int bc   = no + ni * 8 + 2 * t4;
            int col  = colBase + bc;
            int row0 = rowBase + mo + mi * 16 + g;
            int row1 = row0 + 8;
            float2 v0, v1;
            v0.x = acc[mi][ni][0] + sb[bc];
            v0.y = acc[mi][ni][1] + sb[bc + 1];
            v1.x = acc[mi][ni][2] + sb[bc];
            v1.y = acc[mi][ni][3] + sb[bc + 1];
            if (EPI == 0) {
                if (colBase < DINNER) {
                    *reinterpret_cast<__half2*>(&g_xproj[(size_t)row0 * DINNER + col]) =
                        __floats2half2_rn(v0.x, v0.y);
                    *reinterpret_cast<__half2*>(&g_xproj[(size_t)row1 * DINNER + col]) =
                        __floats2half2_rn(v1.x, v1.y);
                } else if (colBase < 2 * DINNER) {
                    int cc = col - DINNER;
                    *reinterpret_cast<__half2*>(&g_delta[(size_t)row0 * DINNER + cc]) =
                        __floats2half2_rn(fmaxf(v0.x, 0.f), fmaxf(v0.y, 0.f));
                    *reinterpret_cast<__half2*>(&g_delta[(size_t)row1 * DINNER + cc]) =
                        __floats2half2_rn(fmaxf(v1.x, 0.f), fmaxf(v1.y, 0.f));
                } else {
                    int cc = col - 2 * DINNER;
                    *reinterpret_cast<__half2*>(&g_gate[(size_t)row0 * DINNER + cc]) =
                        __floats2half2_rn(1.f / (1.f + fexp(-v0.x)),
                                          1.f / (1.f + fexp(-v0.y)));
                    *reinterpret_cast<__half2*>(&g_gate[(size_t)row1 * DINNER + cc]) =
                        __floats2half2_rn(1.f / (1.f + fexp(-v1.x)),
                                          1.f / (1.f + fexp(-v1.y)));
                }
            } else {
                *reinterpret_cast<float2*>(&Cout[(size_t)row0 * N + col]) = v0;
                *reinterpret_cast<float2*>(&Cout[(size_t)row1 * N + col]) = v1;
            }
        }
    }
}

// ---------------------------------------------------------------------------
// Fused fp32 -> fp16 convert for all four source arrays (one launch)
// ---------------------------------------------------------------------------
#define CR0 (TOK * DMODEL / 8)
#define CR1 (2 * DINNER * DMODEL / 8)
#define CR2 (DINNER * DMODEL / 8)
#define CR3 (DMODEL * DINNER / 8)
#define CRT (CR0 + CR1 + CR2 + CR3)

__global__ void __launch_bounds__(256)
conv_all_kernel(const float4* __restrict__ sx, const float4* __restrict__ swi,
                const float4* __restrict__ swg, const float4* __restrict__ swo,
                uint4* __restrict__ dx, uint4* __restrict__ dwi,
                uint4* __restrict__ dwg, uint4* __restrict__ dwo)
{
    int i = blockIdx.x * blockDim.x + threadIdx.x;
    if (i >= CRT) return;
    const float4* s; uint4* d; int off;
    if (i < CR0)                   { s = sx;  d = dx;  off = i; }
    else if (i < CR0 + CR1)        { s = swi; d = dwi; off = i - CR0; }
    else if (i < CR0 + CR1 + CR2)  { s = swg; d = dwg; off = i - CR0 - CR1; }
    else                           { s = swo; d = dwo; off = i - CR0 - CR1 - CR2; }
    float4 u = s[2 * off];
    float4 v = s[2 * off + 1];
    __half2 h0 = __floats2half2_rn(u.x, u.y);
    __half2 h1 = __floats2half2_rn(u.z, u.w);
    __half2 h2 = __floats2half2_rn(v.x, v.y);
    __half2 h3 = __floats2half2_rn(v.z, v.w);
    uint4 o;
    o.x = *reinterpret_cast<uint32_t*>(&h0);
    o.y = *reinterpret_cast<uint32_t*>(&h1);
    o.z = *reinterpret_cast<uint32_t*>(&h2);
    o.w = *reinterpret_cast<uint32_t*>(&h3);
    d[off] = o;
}

// ---------------------------------------------------------------------------
// Chunked selective scan, 4 states/lane, 64 channels/CTA, fp16 SMEM staging.
// B-factored state (r = h/Bs): recurrence r = a*r + u with u = dt*xt.
// scanA: r-chunk + P = exp2(As2 * sum(dt)).  scanC: compose r0, replay,
// p = sum_j r_j * (Bs_j * cs_j), gate, emit fp16.
// ---------------------------------------------------------------------------
#define SCW   64
#define SROWH 72

__global__ void __launch_bounds__(256)
scanA_kernel(const float* __restrict__ A_log)
{
    __shared__ __half sdel[CHL][SROWH];
    __shared__ __half sxp [CHL][SROWH];

    int tid   = threadIdx.x;
    int gidx0 = blockIdx.x * SCW;
    int chunk = gidx0 >> 12;
    int slot0 = gidx0 & (NSLOT - 1);
    int b     = slot0 >> 11;
    int ch0   = slot0 & (DINNER - 1);

    size_t base = (size_t)(b * SEQLEN + chunk * CHL) * DINNER + ch0;

#pragma unroll
    for (int it = 0; it < 2; it++) {
        int seg = tid + it * 256;
        int t   = seg >> 3;
        int c8  = (seg & 7) * 8;
        *reinterpret_cast<uint4*>(&sdel[t][c8]) =
            *reinterpret_cast<const uint4*>(&g_delta[base + (size_t)t * DINNER + c8]);
        *reinterpret_cast<uint4*>(&sxp[t][c8]) =
            *reinterpret_cast<const uint4*>(&g_xproj[base + (size_t)t * DINNER + c8]);
    }
    __syncthreads();

    int grp = tid >> 2;
    int s2  = tid & 3;
    int ch  = ch0 + grp;

    float As2[4];
#pragma unroll
    for (int j = 0; j < 4; j++) {
        int s = s2 * 4 + j;
        As2[j] = -__expf(A_log[ch * DSTATE + s]) * LOG2E;
    }

    float r[4] = {0.f, 0.f, 0.f, 0.f};
    float S = 0.f;
#pragma unroll 4
    for (int t = 0; t < CHL; t++) {
        float dt = __half2float(sdel[t][grp]);
        float xt = __half2float(sxp[t][grp]);
        float u  = dt * xt;
        S += dt;
#pragma unroll
        for (int j = 0; j < 4; j++) {
            float a = exp2f(As2[j] * dt);
            r[j] = fmaf(r[j], a, u);
        }
    }
    float P[4];
#pragma unroll
    for (int j = 0; j < 4; j++) P[j] = exp2f(As2[j] * S);

    size_t o = (size_t)(gidx0 + grp) * DSTATE + s2 * 4;
    *reinterpret_cast<float4*>(&g_P[o]) = make_float4(P[0], P[1], P[2], P[3]);
    *reinterpret_cast<float4*>(&g_r[o]) = make_float4(r[0], r[1], r[2], r[3]);
}

__global__ void __launch_bounds__(256)
scanC_kernel(const float* __restrict__ A_log, const float* __restrict__ B_mat,
             const float* __restrict__ C_mat, const float* __restrict__ D_vec)
{
    __shared__ __half sdel[CHL][SROWH];
    __shared__ __half sxp [CHL][SROWH];
    __shared__ __half sgt [CHL][SROWH];
    __shared__ __half sout[CHL][SCW];

    int tid   = threadIdx.x;
    int gidx0 = blockIdx.x * SCW;
    int chunk = gidx0 >> 12;
    int slot0 = gidx0 & (NSLOT - 1);
    int b     = slot0 >> 11;
    int ch0   = slot0 & (DINNER - 1);

    size_t base = (size_t)(b * SEQLEN + chunk * CHL) * DINNER + ch0;

#pragma unroll
    for (int it = 0; it < 2; it++) {
        int seg = tid + it * 256;
        int t   = seg >> 3;
        int c8  = (seg & 7) * 8;
        *reinterpret_cast<uint4*>(&sdel[t][c8]) =
            *reinterpret_cast<const uint4*>(&g_delta[base + (size_t)t * DINNER + c8]);
        *reinterpret_cast<uint4*>(&sxp[t][c8]) =
            *reinterpret_cast<const uint4*>(&g_xproj[base + (size_t)t * DINNER + c8]);
        *reinterpret_cast<uint4*>(&sgt[t][c8]) =
            *reinterpret_cast<const uint4*>(&g_gate[base + (size_t)t * DINNER + c8]);
    }

    int grp  = tid >> 2;
    int s2   = tid & 3;
    int ch   = ch0 + grp;
    int slot = slot0 + grp;

    float As2[4], bc[4];
#pragma unroll
    for (int j = 0; j < 4; j++) {
        int s = s2 * 4 + j;
        As2[j] = -__expf(A_log[ch * DSTATE + s]) * LOG2E;
        bc[j]  = B_mat[ch * DSTATE + s] * C_mat[s];   // combined output weight
    }
    float Dch = D_vec[ch];

    // self-compose r0 from per-chunk (P, r)
    float r[4] = {0.f, 0.f, 0.f, 0.f};
    for (int j = 0; j < chunk; j++) {
        size_t o = ((size_t)(j << 12) + slot) * DSTATE + s2 * 4;
        float4 P4 = *reinterpret_cast<const float4*>(&g_P[o]);
        float4 r4 = *reinterpret_cast<const float4*>(&g_r[o]);
        r[0] = fmaf(P4.x, r[0], r4.x);
        r[1] = fmaf(P4.y, r[1], r4.y);
        r[2] = fmaf(P4.z, r[2], r4.z);
        r[3] = fmaf(P4.w, r[3], r4.w);
    }

    __syncthreads();

#pragma unroll 4
    for (int t = 0; t < CHL; t++) {
        float dt = __half2float(sdel[t][grp]);
        float xt = __half2float(sxp[t][grp]);
        float u  = dt * xt;
        float p  = 0.f;
#pragma unroll
        for (int j = 0; j < 4; j++) {
            float a = exp2f(As2[j] * dt);
            r[j] = fmaf(r[j], a, u);
            p = fmaf(r[j], bc[j], p);
        }
        p += __shfl_xor_sync(0xffffffffu, p, 1);
        p += __shfl_xor_sync(0xffffffffu, p, 2);
        if (s2 == 0) {
            float v = __half2float(sgt[t][grp]) * (p + xt * Dch);
            sout[t][grp] = __float2half(v);
        }
    }
    __syncthreads();

    {
        int t = tid >> 2;
        int c = (tid & 3) * 16;
        *reinterpret_cast<uint4*>(&g_gss[base + (size_t)t * DINNER + c]) =
            *reinterpret_cast<const uint4*>(&sout[t][c]);
        *reinterpret_cast<uint4*>(&g_gss[base + (size_t)t * DINNER + c + 8]) =
            *reinterpret_cast<const uint4*>(&sout[t][c + 8]);
    }
}

// ---------------------------------------------------------------------------
extern "C" void kernel_launch(void* const* d_in, const int* in_sizes, int n_in,
                              void* d_out, int out_size)
{
    const float* x      = (const float*)d_in[0];
    const float* W_in   = (const float*)d_in[1];
    const float* b_in   = (const float*)d_in[2];
    const float* W_gate = (const float*)d_in[3];
    const float* b_gate = (const float*)d_in[4];
    const float* W_out  = (const float*)d_in[5];
    const float* b_out  = (const float*)d_in[6];
    const float* A_log  = (const float*)d_in[7];
    const float* B_mat  = (const float*)d_in[8];
    const float* C_mat  = (const float*)d_in[9];
    const float* D_vec  = (const float*)d_in[10];
    float* out = (float*)d_out;

    cudaFuncSetAttribute((const void*)gemm_mma<0, 128>,
                         cudaFuncAttributeMaxDynamicSharedMemorySize, SMEMT(128));
    cudaFuncSetAttribute((const void*)gemm_mma<2, 64>,
                         cudaFuncAttributeMaxDynamicSharedMemorySize, SMEMT(64));

    __half *xh, *wi, *wo, *gs;
    cudaGetSymbolAddress((void**)&xh, g_x);
    cudaGetSymbolAddress((void**)&wi, g_wi);
    cudaGetSymbolAddress((void**)&wo, g_wo);
    cudaGetSymbolAddress((void**)&gs, g_gss);

    const size_t WG_OFF = (size_t)2 * DINNER * DMODEL;

    // 1) fused fp32 -> fp16 converts
    conv_all_kernel<<<(CRT + 255) / 256, 256>>>(
        (const float4*)x, (const float4*)W_in, (const float4*)W_gate, (const float4*)W_out,
        (uint4*)xh, (uint4*)wi, (uint4*)(wi + WG_OFF), (uint4*)wo);

    // 2) fused in-proj + gate GEMM (N = 6144), fp16 epilogue
    gemm_mma<0, 128><<<dim3(NIN / 128, TOK / 128), 256, SMEMT(128)>>>(
        xh, wi, b_in, b_gate, nullptr, NIN, DMODEL);

    // 3) chunked selective scan (B-factored, 4 states/lane)
    scanA_kernel<<<(CHK * NSLOT) / SCW, 256>>>(A_log);
    scanC_kernel<<<(CHK * NSLOT) / SCW, 256>>>(A_log, B_mat, C_mat, D_vec);

    // 4) out = gss @ W_out^T + b_out  (BM=64 -> 256 CTAs)
    gemm_mma<2, 64><<<dim3(DMODEL / 128, TOK / 64), 256, SMEMT(64)>>>(
        gs, wo, b_out, nullptr, out, DMODEL, DINNER);
}